// round 12
// baseline (speedup 1.0000x reference)
#include <cuda_runtime.h>
#include <cuda_fp16.h>
#include <cstdint>

#define T_TOK 4096
#define HID   2048
#define QD    2048
#define INTER_N 10944

// ---------------- scratch (__device__ globals; no allocs allowed) ----------------
__device__ __half g_w16q[(size_t)QD * HID];
__device__ __half g_w16o[(size_t)HID * QD];
__device__ __half g_w16g[(size_t)INTER_N * HID];
__device__ __half g_w16u[(size_t)INTER_N * HID];
__device__ __half g_w16d[(size_t)HID * INTER_N];
// A-operands in blocked MMA-fragment layout: per 16x16 block, 32 lanes x uint4 (a0..a3)
__device__ uint4 g_a16h[(size_t)T_TOK * HID / 8];      // rmsnorm(x)
__device__ uint4 g_a16q[(size_t)T_TOK * QD / 8];       // q
__device__ uint4 g_a16p[(size_t)T_TOK * HID / 8];      // rmsnorm(hidden)
__device__ uint4 g_a16m[(size_t)T_TOK * INTER_N / 8];  // silu(gate)*up
__device__ float g_hidden[(size_t)T_TOK * HID];
__device__ float g_prodf[(size_t)T_TOK * INTER_N];     // silu(gate) fp32

// ---------------- PTX helpers ----------------
__device__ __forceinline__ uint32_t smem_u32(const void* p) {
    uint32_t a;
    asm("{ .reg .u64 t; cvta.to.shared.u64 t, %1; cvt.u32.u64 %0, t; }" : "=r"(a) : "l"(p));
    return a;
}
#define CP16(dst, src)   asm volatile("cp.async.cg.shared.global [%0], [%1], 16;" :: "r"(dst), "l"(src) : "memory")
#define CP_COMMIT()      asm volatile("cp.async.commit_group;" ::: "memory")
#define CP_WAIT3()       asm volatile("cp.async.wait_group 3;" ::: "memory")

__device__ __forceinline__ void ldm_x4(uint32_t* r, uint32_t addr) {
    asm volatile("ldmatrix.sync.aligned.m8n8.x4.shared.b16 {%0,%1,%2,%3}, [%4];"
                 : "=r"(r[0]), "=r"(r[1]), "=r"(r[2]), "=r"(r[3]) : "r"(addr));
}
__device__ __forceinline__ void mma_fp16(float* c, const uint32_t* a, const uint32_t* b) {
    asm volatile(
        "mma.sync.aligned.m16n8k16.row.col.f32.f16.f16.f32 "
        "{%0,%1,%2,%3}, {%4,%5,%6,%7}, {%8,%9}, {%0,%1,%2,%3};"
        : "+f"(c[0]), "+f"(c[1]), "+f"(c[2]), "+f"(c[3])
        : "r"(a[0]), "r"(a[1]), "r"(a[2]), "r"(a[3]), "r"(b[0]), "r"(b[1]));
}
__device__ __forceinline__ uint32_t packh2(float a, float b) {
    __half2 h = __floats2half2_rn(a, b);
    return *(uint32_t*)&h;
}

// ---------------- weight convert: fp32 -> fp16 (8 elems/thread/iter) ----------------
__global__ void cvt_w_kernel(const float4* __restrict__ W, uint4* __restrict__ O,
                             unsigned total8) {
    unsigned i = blockIdx.x * blockDim.x + threadIdx.x;
    const unsigned stride = gridDim.x * blockDim.x;
    for (; i < total8; i += stride) {
        float4 v0 = W[i * 2];
        float4 v1 = W[i * 2 + 1];
        uint4 o;
        o.x = packh2(v0.x, v0.y); o.y = packh2(v0.z, v0.w);
        o.z = packh2(v1.x, v1.y); o.w = packh2(v1.z, v1.w);
        O[i] = o;
    }
}

// ---------------- RMSNorm -> fp16 blocked-fragment layout ----------------
__global__ void rmsnorm_f16_blk(const float* __restrict__ x,
                                const float* __restrict__ w,
                                uint4* __restrict__ out) {
    const int row = blockIdx.x;
    const float4* xr = (const float4*)(x + (size_t)row * HID);
    const float4* wv4 = (const float4*)w;

    float4 v[2];
    float ss = 0.f;
#pragma unroll
    for (int i = 0; i < 2; i++) {
        v[i] = xr[threadIdx.x + i * 256];
        ss += v[i].x * v[i].x + v[i].y * v[i].y + v[i].z * v[i].z + v[i].w * v[i].w;
    }
#pragma unroll
    for (int o = 16; o; o >>= 1) ss += __shfl_xor_sync(0xffffffffu, ss, o);
    __shared__ float sred[8];
    if ((threadIdx.x & 31) == 0) sred[threadIdx.x >> 5] = ss;
    __syncthreads();
    if (threadIdx.x < 8) {
        float t = sred[threadIdx.x];
#pragma unroll
        for (int o = 4; o; o >>= 1) t += __shfl_xor_sync(0xffu, t, o);
        if (threadIdx.x == 0) sred[0] = t;
    }
    __syncthreads();
    const float scale = rsqrtf(sred[0] * (1.0f / HID) + 1e-6f);

    uint32_t* ow = (uint32_t*)out;
    const uint32_t MBbase = (uint32_t)(row >> 4) * 128u;   // MB * nKB (nKB=128 for HID)
    const uint32_t lanebase = (uint32_t)((row & 7) << 2);
    const uint32_t reg0 = (uint32_t)((row >> 3) & 1);
#pragma unroll
    for (int i = 0; i < 2; i++) {
        float4 wv = wv4[threadIdx.x + i * 256];
        const int c0 = (threadIdx.x + i * 256) * 4;
        uint32_t pr[2];
        pr[0] = packh2(v[i].x * scale * wv.x, v[i].y * scale * wv.y);
        pr[1] = packh2(v[i].z * scale * wv.z, v[i].w * scale * wv.w);
#pragma unroll
        for (int p = 0; p < 2; p++) {
            const int colp = c0 + 2 * p;
            const uint32_t KB = (uint32_t)(colp >> 4);
            const uint32_t cw = (uint32_t)(colp & 15);
            const uint32_t idx = ((MBbase + KB) << 7)
                               + ((lanebase + ((cw & 7) >> 1)) << 2)
                               + reg0 + ((cw >> 3) << 1);
            ow[idx] = pr[p];
        }
    }
}

// ---------------- HMMA GEMM: C[m,n] = epi(sum_k A[m,k]*B[n,k]), fp16 ----------------
// A: blocked-fragment uint4 layout, coalesced LDG.128, prefetched a chunk ahead.
// B: [N][K] fp16 row-major via 5-stage cp.async + SW128 + ldmatrix.
// CTA tile 128x128, 128 threads (4 warps, 2m x 2n), warp tile 64x64, BK=64.
// EPI: 1 = silu->C(f32) ; 2 = acc*C -> Dst(blocked f16) ; 3 = acc+Res -> C(f32) ; 4 = Dst(blocked f16)
#define NSTAGE 5
#define B_STG  16384                 // 128 rows * 128B
#define SMEM_TOTAL (NSTAGE * B_STG)  // 80KB

template <int EPI>
__global__ void __launch_bounds__(128, 2)
gemm_f16(const uint4* __restrict__ Ablk, const __half* __restrict__ B,
         float* __restrict__ C, const float* __restrict__ Res,
         uint4* __restrict__ Dst, int N, int K) {
    extern __shared__ __align__(1024) char smem[];
    const uint32_t sb = smem_u32(smem);
    const int tid = threadIdx.x;
    const int lane = tid & 31;
    const int w = tid >> 5;
    const int mw = w >> 1;            // 0..1  (64-row slab)
    const int nw = w & 1;             // 0..1  (64-col slab)
    const int bm = blockIdx.y * 128;
    const int bn = blockIdx.x * 128;
    const int nch = K >> 6;           // 64-elem chunks
    const uint32_t nKB32 = (uint32_t)(K >> 4) << 5;   // nKB * 32 (uint4 units per MB row)

    // ---- B loader: 8 x 16B per thread ----
    const char* Bbase = (const char*)B;
    const int lr = tid >> 3;                    // 0..15
    const int lc = tid & 7;                     // 0..7
    const uint32_t l_dst0 = (uint32_t)(lr * 128 + ((lc * 16) ^ ((lr & 7) << 4)));
    uint32_t b_off[8];
#pragma unroll
    for (int i = 0; i < 8; i++) {
        int gr = bn + lr + 16 * i; if (gr > N - 1) gr = N - 1;
        b_off[i] = ((uint32_t)gr * (uint32_t)K + (uint32_t)lc * 8u) * 2u;
    }
    auto loadB = [&](int stage, int ch) {
        const uint32_t co = (uint32_t)ch * 128u;
        uint32_t bb = sb + stage * B_STG + l_dst0;
#pragma unroll
        for (int i = 0; i < 8; i++) CP16(bb + (uint32_t)(i * 2048), Bbase + b_off[i] + co);
        CP_COMMIT();
    };

    // ---- B ldmatrix lane addressing ----
    const int brow = nw * 64 + ((lane >> 4) & 1) * 8 + (lane & 7);
    const uint32_t b_xor = (uint32_t)((brow & 7) << 4);
    const uint32_t b_rb = (uint32_t)(brow * 128);
    const uint32_t b_k0 = (uint32_t)(((lane >> 3) & 1) * 16);

    // ---- A fragment loader (blocked layout, double-buffered across chunks) ----
    const uint32_t MB0 = (uint32_t)((bm >> 4) + mw * 4);
    const uint4* pA0 = Ablk + (size_t)MB0 * nKB32 + lane;
    uint32_t af[2][4][4][4];   // [buf][kk][ma][reg]
    auto loadA = [&](int buf, int ch) {
#pragma unroll
        for (int ma = 0; ma < 4; ma++)
#pragma unroll
            for (int kk = 0; kk < 4; kk++) {
                uint4 t = pA0[(size_t)ma * nKB32 + (uint32_t)(((ch << 2) + kk) << 5)];
                af[buf][kk][ma][0] = t.x; af[buf][kk][ma][1] = t.y;
                af[buf][kk][ma][2] = t.z; af[buf][kk][ma][3] = t.w;
            }
    };

    float acc[4][8][4];
#pragma unroll
    for (int i = 0; i < 4; i++)
#pragma unroll
        for (int j = 0; j < 8; j++)
#pragma unroll
            for (int q = 0; q < 4; q++) acc[i][j][q] = 0.f;

    // ---- pipeline ----
    loadB(0, 0); loadB(1, 1); loadB(2, 2); loadB(3, 3);
    loadA(0, 0);

    for (int s = 0; s < nch; s++) {
        CP_WAIT3();                   // B chunk s resident
        __syncthreads();              // all warps done reading stage (s-1)%5

        const int nc = s + 4;
        if (nc < nch) loadB(nc % NSTAGE, nc);
        else          CP_COMMIT();    // empty group keeps wait accounting exact

        // issue next chunk's A LDGs early so they overlap this chunk's MMAs
        const int cur = s & 1;
        if (s + 1 < nch) loadA(cur ^ 1, s + 1);

        const uint32_t sB = sb + (s % NSTAGE) * B_STG;
#pragma unroll
        for (int kk = 0; kk < 4; kk++) {
            uint32_t bf[4][4];
#pragma unroll
            for (int nb = 0; nb < 4; nb++)
                ldm_x4(bf[nb], sB + b_rb + (uint32_t)(nb * 2048) + ((kk * 32 + b_k0) ^ b_xor));
#pragma unroll
            for (int ma = 0; ma < 4; ma++)
#pragma unroll
                for (int na = 0; na < 8; na++)
                    mma_fp16(acc[ma][na], af[cur][kk][ma], &bf[na >> 1][(na & 1) * 2]);
        }
    }

    // ---- epilogue ----
    if (EPI == 2 || EPI == 4) {
        // blocked-fragment output (Dst is next GEMM's A)
        const uint32_t nKBo = (uint32_t)N >> 4;
#pragma unroll
        for (int ma = 0; ma < 4; ma++) {
            const int gmr = bm + mw * 64 + ma * 16 + (lane >> 2);
            const uint32_t MB = (uint32_t)((bm + mw * 64 + ma * 16) >> 4);
#pragma unroll
            for (int p = 0; p < 4; p++) {
                const int col0 = bn + nw * 64 + p * 16;
                if (col0 >= N) continue;
                float v[2][4];
#pragma unroll
                for (int q = 0; q < 2; q++) {
                    const int na = 2 * p + q;
#pragma unroll
                    for (int ci = 0; ci < 4; ci++) v[q][ci] = acc[ma][na][ci];
                    if (EPI == 2) {
                        const int gn = col0 + q * 8 + (lane & 3) * 2;
#pragma unroll
                        for (int h = 0; h < 2; h++) {
                            float2 g = *(const float2*)(C + (size_t)(gmr + 8 * h) * N + gn);
                            v[q][2 * h + 0] *= g.x;
                            v[q][2 * h + 1] *= g.y;
                        }
                    }
                }
                uint4 o;
                o.x = packh2(v[0][0], v[0][1]);
                o.y = packh2(v[0][2], v[0][3]);
                o.z = packh2(v[1][0], v[1][1]);
                o.w = packh2(v[1][2], v[1][3]);
                const uint32_t KB = (uint32_t)col0 >> 4;
                Dst[(size_t)(MB * nKBo + KB) * 32 + lane] = o;
            }
        }
    } else {
#pragma unroll
        for (int ma = 0; ma < 4; ma++) {
            const int gm0 = bm + mw * 64 + ma * 16 + (lane >> 2);
#pragma unroll
            for (int na = 0; na < 8; na++) {
                const int gn = bn + nw * 64 + na * 8 + (lane & 3) * 2;
                if (gn >= N) continue;
                const float* c = acc[ma][na];
#pragma unroll
                for (int h = 0; h < 2; h++) {
                    const int gm = gm0 + h * 8;
                    float v0 = c[h * 2 + 0], v1 = c[h * 2 + 1];
                    if (EPI == 1) {
                        float2 o;
                        o.x = v0 / (1.f + __expf(-v0));
                        o.y = v1 / (1.f + __expf(-v1));
                        *(float2*)(C + (size_t)gm * N + gn) = o;
                    } else {  // EPI == 3
                        float2 rr = *(const float2*)(Res + (size_t)gm * N + gn);
                        float2 o; o.x = v0 + rr.x; o.y = v1 + rr.y;
                        *(float2*)(C + (size_t)gm * N + gn) = o;
                    }
                }
            }
        }
    }
}

// ---------------- launch ----------------
extern "C" void kernel_launch(void* const* d_in, const int* in_sizes, int n_in,
                              void* d_out, int out_size) {
    const float* x      = (const float*)d_in[0];
    const float* in_w   = (const float*)d_in[2];
    const float* post_w = (const float*)d_in[3];
    const float* Wq     = (const float*)d_in[4];
    const float* Wo     = (const float*)d_in[5];
    const float* Wg     = (const float*)d_in[6];
    const float* Wu     = (const float*)d_in[7];
    const float* Wd     = (const float*)d_in[8];
    float* out = (float*)d_out;

    __half *w16q, *w16o, *w16g, *w16u, *w16d;
    uint4 *a16h, *a16q, *a16p, *a16m;
    float *hidden, *prodf;
    cudaGetSymbolAddress((void**)&w16q, g_w16q);
    cudaGetSymbolAddress((void**)&w16o, g_w16o);
    cudaGetSymbolAddress((void**)&w16g, g_w16g);
    cudaGetSymbolAddress((void**)&w16u, g_w16u);
    cudaGetSymbolAddress((void**)&w16d, g_w16d);
    cudaGetSymbolAddress((void**)&a16h, g_a16h);
    cudaGetSymbolAddress((void**)&a16q, g_a16q);
    cudaGetSymbolAddress((void**)&a16p, g_a16p);
    cudaGetSymbolAddress((void**)&a16m, g_a16m);
    cudaGetSymbolAddress((void**)&hidden, g_hidden);
    cudaGetSymbolAddress((void**)&prodf, g_prodf);

    cudaFuncSetAttribute(gemm_f16<1>, cudaFuncAttributeMaxDynamicSharedMemorySize, SMEM_TOTAL);
    cudaFuncSetAttribute(gemm_f16<2>, cudaFuncAttributeMaxDynamicSharedMemorySize, SMEM_TOTAL);
    cudaFuncSetAttribute(gemm_f16<3>, cudaFuncAttributeMaxDynamicSharedMemorySize, SMEM_TOTAL);
    cudaFuncSetAttribute(gemm_f16<4>, cudaFuncAttributeMaxDynamicSharedMemorySize, SMEM_TOTAL);

    const int MT = T_TOK / 128;  // 32

    // Launch order puts the q-GEMM at index 5 so ncu (-s 5 -c 1) captures it.
    // 0: input_layernorm -> blocked fp16
    rmsnorm_f16_blk<<<T_TOK, 256>>>(x, in_w, a16h);
    // 1-4: weight converts needed before q/o/gate/up
    cvt_w_kernel<<<2048, 256>>>((const float4*)Wq, (uint4*)w16q, (unsigned)((size_t)QD * HID / 8));
    cvt_w_kernel<<<2048, 256>>>((const float4*)Wo, (uint4*)w16o, (unsigned)((size_t)HID * QD / 8));
    cvt_w_kernel<<<2048, 256>>>((const float4*)Wg, (uint4*)w16g, (unsigned)((size_t)INTER_N * HID / 8));
    cvt_w_kernel<<<2048, 256>>>((const float4*)Wu, (uint4*)w16u, (unsigned)((size_t)INTER_N * HID / 8));
    // 5: q = hnorm @ Wq^T -> blocked fp16   (ncu capture target)
    gemm_f16<4><<<dim3(QD / 128, MT), 128, SMEM_TOTAL>>>(a16h, w16q, nullptr, nullptr, a16q, QD, HID);
    // 6: hidden = x + q @ Wo^T
    gemm_f16<3><<<dim3(HID / 128, MT), 128, SMEM_TOTAL>>>(a16q, w16o, hidden, x, nullptr, HID, QD);
    // 7: post_attention_layernorm -> blocked fp16
    rmsnorm_f16_blk<<<T_TOK, 256>>>(hidden, post_w, a16p);
    // 8: convert Wd (only needed by launch 11)
    cvt_w_kernel<<<2048, 256>>>((const float4*)Wd, (uint4*)w16d, (unsigned)((size_t)HID * INTER_N / 8));
    // 9: prodf = silu(hpost @ Wg^T)  (fp32)
    gemm_f16<1><<<dim3((INTER_N + 127) / 128, MT), 128, SMEM_TOTAL>>>(a16p, w16g, prodf, nullptr, nullptr, INTER_N, HID);
    // 10: a16m = blocked fp16(prodf * (hpost @ Wu^T))
    gemm_f16<2><<<dim3((INTER_N + 127) / 128, MT), 128, SMEM_TOTAL>>>(a16p, w16u, prodf, nullptr, a16m, INTER_N, HID);
    // 11: out = hidden + a16m @ Wd^T
    gemm_f16<3><<<dim3(HID / 128, MT), 128, SMEM_TOTAL>>>(a16m, w16d, out, hidden, nullptr, HID, INTER_N);
}

// round 14
// speedup vs baseline: 2.7140x; 2.7140x over previous
#include <cuda_runtime.h>
#include <cuda_fp16.h>
#include <cstdint>

#define T_TOK 4096
#define HID   2048
#define QD    2048
#define INTER_N 10944

// ---------------- scratch (__device__ globals; no allocs allowed) ----------------
__device__ __half g_w16q[(size_t)QD * HID];
__device__ __half g_w16o[(size_t)HID * QD];
__device__ __half g_w16g[(size_t)INTER_N * HID];
__device__ __half g_w16u[(size_t)INTER_N * HID];
__device__ __half g_w16d[(size_t)HID * INTER_N];
__device__ __half g_a16h[(size_t)T_TOK * HID];     // rmsnorm(x) fp16
__device__ __half g_a16q[(size_t)T_TOK * QD];      // q fp16
__device__ __half g_a16p[(size_t)T_TOK * HID];     // rmsnorm(hidden) fp16
__device__ __half g_a16m[(size_t)T_TOK * INTER_N]; // silu(gate)*up fp16
__device__ __half g_prod16[(size_t)T_TOK * INTER_N]; // silu(gate) fp16
__device__ float g_hidden[(size_t)T_TOK * HID];

// ---------------- PTX helpers ----------------
__device__ __forceinline__ uint32_t smem_u32(const void* p) {
    uint32_t a;
    asm("{ .reg .u64 t; cvta.to.shared.u64 t, %1; cvt.u32.u64 %0, t; }" : "=r"(a) : "l"(p));
    return a;
}
#define CP16(dst, src)   asm volatile("cp.async.cg.shared.global [%0], [%1], 16;" :: "r"(dst), "l"(src) : "memory")
#define CP_COMMIT()      asm volatile("cp.async.commit_group;" ::: "memory")
#define CP_WAIT1()       asm volatile("cp.async.wait_group 1;" ::: "memory")

__device__ __forceinline__ void ldm_x4(uint32_t* r, uint32_t addr) {
    asm volatile("ldmatrix.sync.aligned.m8n8.x4.shared.b16 {%0,%1,%2,%3}, [%4];"
                 : "=r"(r[0]), "=r"(r[1]), "=r"(r[2]), "=r"(r[3]) : "r"(addr));
}
__device__ __forceinline__ void mma_fp16(float* c, const uint32_t* a, const uint32_t* b) {
    asm volatile(
        "mma.sync.aligned.m16n8k16.row.col.f32.f16.f16.f32 "
        "{%0,%1,%2,%3}, {%4,%5,%6,%7}, {%8,%9}, {%0,%1,%2,%3};"
        : "+f"(c[0]), "+f"(c[1]), "+f"(c[2]), "+f"(c[3])
        : "r"(a[0]), "r"(a[1]), "r"(a[2]), "r"(a[3]), "r"(b[0]), "r"(b[1]));
}
__device__ __forceinline__ uint32_t packh2(float a, float b) {
    __half2 h = __floats2half2_rn(a, b);
    return *(uint32_t*)&h;
}

// ---------------- single fused weight convert: all 5 weights, fp32 -> fp16 ----------------
// Flat index space over uint4 outputs (8 halfs each); 5 segments.
__global__ void cvt_all_kernel(const float4* __restrict__ Wq, uint4* __restrict__ Oq,
                               const float4* __restrict__ Wo, uint4* __restrict__ Oo,
                               const float4* __restrict__ Wg, uint4* __restrict__ Og,
                               const float4* __restrict__ Wu, uint4* __restrict__ Ou,
                               const float4* __restrict__ Wd, uint4* __restrict__ Od,
                               unsigned e0, unsigned e1, unsigned e2, unsigned e3,
                               unsigned total8) {
    unsigned i = blockIdx.x * blockDim.x + threadIdx.x;
    const unsigned stride = gridDim.x * blockDim.x;
    for (; i < total8; i += stride) {
        const float4* s; uint4* d; unsigned off;
        if (i < e0)      { s = Wq; d = Oq; off = i; }
        else if (i < e1) { s = Wo; d = Oo; off = i - e0; }
        else if (i < e2) { s = Wg; d = Og; off = i - e1; }
        else if (i < e3) { s = Wu; d = Ou; off = i - e2; }
        else             { s = Wd; d = Od; off = i - e3; }
        float4 v0 = s[off * 2];
        float4 v1 = s[off * 2 + 1];
        uint4 o;
        o.x = packh2(v0.x, v0.y); o.y = packh2(v0.z, v0.w);
        o.z = packh2(v1.x, v1.y); o.w = packh2(v1.z, v1.w);
        d[off] = o;
    }
}

// ---------------- RMSNorm -> fp16 ----------------
__global__ void rmsnorm_f16_kernel(const float* __restrict__ x,
                                   const float* __restrict__ w,
                                   __half* __restrict__ out) {
    const int row = blockIdx.x;
    const float4* xr = (const float4*)(x + (size_t)row * HID);
    const float4* wv4 = (const float4*)w;

    float4 v[2];
    float ss = 0.f;
#pragma unroll
    for (int i = 0; i < 2; i++) {
        v[i] = xr[threadIdx.x + i * 256];
        ss += v[i].x * v[i].x + v[i].y * v[i].y + v[i].z * v[i].z + v[i].w * v[i].w;
    }
#pragma unroll
    for (int o = 16; o; o >>= 1) ss += __shfl_xor_sync(0xffffffffu, ss, o);
    __shared__ float sred[8];
    if ((threadIdx.x & 31) == 0) sred[threadIdx.x >> 5] = ss;
    __syncthreads();
    if (threadIdx.x < 8) {
        float t = sred[threadIdx.x];
#pragma unroll
        for (int o = 4; o; o >>= 1) t += __shfl_xor_sync(0xffu, t, o);
        if (threadIdx.x == 0) sred[0] = t;
    }
    __syncthreads();
    const float scale = rsqrtf(sred[0] * (1.0f / HID) + 1e-6f);

    uint2* orow = (uint2*)(out + (size_t)row * HID);
#pragma unroll
    for (int i = 0; i < 2; i++) {
        float4 wv = wv4[threadIdx.x + i * 256];
        uint2 o;
        o.x = packh2(v[i].x * scale * wv.x, v[i].y * scale * wv.y);
        o.y = packh2(v[i].z * scale * wv.z, v[i].w * scale * wv.w);
        orow[threadIdx.x + i * 256] = o;
    }
}

// ---------------- HMMA GEMM: C[m,n] = epi(sum_k A[m,k]*B[n,k]), fp16 ----------------
// CTA tile 128x128, 128 threads (4 warps, 2m x 2n), warp tile 64x64, BK=64.
// 3-stage cp.async pipeline (96KB smem, 2 CTAs/SM), SW128 swizzle,
// ldmatrix double-buffered across kk + mma.m16n8k16.  (R9 mainloop, unchanged.)
// EPI: 1 = silu -> Dst(f16) ; 2 = acc*G -> Dst(f16) ; 3 = acc+Res -> C(f32) ; 4 = Dst(f16)
#define NSTAGE 3
#define A_BYTES 16384               // 128 rows * 128B
#define STG     32768               // A 16KB + B 16KB
#define SMEM_TOTAL (NSTAGE * STG)   // 96KB

template <int EPI>
__global__ void __launch_bounds__(128, 2)
gemm_f16(const __half* __restrict__ A, const __half* __restrict__ B,
         float* __restrict__ C, const float* __restrict__ Res,
         __half* __restrict__ Dst, const __half* __restrict__ G, int N, int K) {
    extern __shared__ __align__(1024) char smem[];
    const uint32_t sb = smem_u32(smem);
    const int tid = threadIdx.x;
    const int lane = tid & 31;
    const int w = tid >> 5;
    const int mw = w >> 1;            // 0..1  (64-row slab)
    const int nw = w & 1;             // 0..1  (64-col slab)
    const int bm = blockIdx.y * 128;
    const int bn = blockIdx.x * 128;
    const int nch = K >> 6;           // 64-elem chunks
    const uint32_t strideK = (uint32_t)K;
    const uint32_t rowskip16 = strideK * 32u;   // 16 rows * K halves * 2B

    // ---- loader: 16 x 16B per thread (8 for A, 8 for B); strided form ----
    const char* Abase = (const char*)A;
    const char* Bbase = (const char*)B;
    const int lr = tid >> 3;                    // 0..15
    const int lc = tid & 7;                     // 0..7
    const uint32_t l_dst0 = (uint32_t)(lr * 128 + ((lc * 16) ^ ((lr & 7) << 4)));
    const uint32_t a_off0 = ((uint32_t)(bm + lr) * strideK + (uint32_t)lc * 8u) * 2u;
    uint32_t b_off[8];
#pragma unroll
    for (int i = 0; i < 8; i++) {
        int gr = bn + lr + 16 * i; if (gr > N - 1) gr = N - 1;
        b_off[i] = ((uint32_t)gr * strideK + (uint32_t)lc * 8u) * 2u;
    }

    auto load_stage = [&](int stage, int ch) {
        const uint32_t co = (uint32_t)ch * 128u;   // 64 halfs = 128 bytes
        uint32_t ab = sb + stage * STG + l_dst0;
        uint32_t bb = ab + A_BYTES;
        const char* ap = Abase + a_off0 + co;
        const char* bp = Bbase + co;
#pragma unroll
        for (int i = 0; i < 8; i++) CP16(ab + (uint32_t)(i * 2048), ap + (size_t)i * rowskip16);
#pragma unroll
        for (int i = 0; i < 8; i++) CP16(bb + (uint32_t)(i * 2048), bp + b_off[i]);
        CP_COMMIT();
    };

    // ---- ldmatrix lane addressing ----
    const int arow = mw * 64 + (lane & 15);
    const uint32_t a_xor = (uint32_t)((arow & 7) << 4);
    const uint32_t a_rb = (uint32_t)(arow * 128);
    const uint32_t a_k0 = (uint32_t)((lane >> 4) * 16);
    const int brow = nw * 64 + ((lane >> 4) & 1) * 8 + (lane & 7);
    const uint32_t b_xor = (uint32_t)((brow & 7) << 4);
    const uint32_t b_rb = (uint32_t)(brow * 128);
    const uint32_t b_k0 = (uint32_t)(((lane >> 3) & 1) * 16);

    float acc[4][8][4];
#pragma unroll
    for (int i = 0; i < 4; i++)
#pragma unroll
        for (int j = 0; j < 8; j++)
#pragma unroll
            for (int q = 0; q < 4; q++) acc[i][j][q] = 0.f;

    uint32_t af[2][4][4], bf[2][4][4];

    // ---- pipeline ----
    load_stage(0, 0);
    load_stage(1, 1);

    for (int s = 0; s < nch; s++) {
        const int stage = s % NSTAGE;
        CP_WAIT1();                   // chunk s resident
        __syncthreads();              // stage (s-1)%3 == (s+2)%3 free for reuse

        const int nc = s + 2;
        if (nc < nch) load_stage(nc % NSTAGE, nc);
        else          CP_COMMIT();    // empty group keeps wait accounting exact

        const uint32_t sA = sb + stage * STG;
        const uint32_t sB = sA + A_BYTES;

        // prime kk=0 fragments
#pragma unroll
        for (int ma = 0; ma < 4; ma++)
            ldm_x4(af[0][ma], sA + a_rb + (uint32_t)(ma * 2048) + (a_k0 ^ a_xor));
#pragma unroll
        for (int nb = 0; nb < 4; nb++)
            ldm_x4(bf[0][nb], sB + b_rb + (uint32_t)(nb * 2048) + (b_k0 ^ b_xor));

#pragma unroll
        for (int kk = 0; kk < 4; kk++) {
            const int cur = kk & 1, nxt = cur ^ 1;
            if (kk < 3) {   // prefetch next kk's fragments under this kk's MMAs
#pragma unroll
                for (int ma = 0; ma < 4; ma++)
                    ldm_x4(af[nxt][ma], sA + a_rb + (uint32_t)(ma * 2048) + (((kk + 1) * 32 + a_k0) ^ a_xor));
#pragma unroll
                for (int nb = 0; nb < 4; nb++)
                    ldm_x4(bf[nxt][nb], sB + b_rb + (uint32_t)(nb * 2048) + (((kk + 1) * 32 + b_k0) ^ b_xor));
            }
#pragma unroll
            for (int ma = 0; ma < 4; ma++)
#pragma unroll
                for (int na = 0; na < 8; na++)
                    mma_fp16(acc[ma][na], af[cur][ma], &bf[cur][na >> 1][(na & 1) * 2]);
        }
    }

    // ---- epilogue ----
#pragma unroll
    for (int ma = 0; ma < 4; ma++) {
        const int gm0 = bm + mw * 64 + ma * 16 + (lane >> 2);
#pragma unroll
        for (int na = 0; na < 8; na++) {
            const int gn = bn + nw * 64 + na * 8 + (lane & 3) * 2;
            if (gn >= N) continue;
            const float* c = acc[ma][na];
#pragma unroll
            for (int h = 0; h < 2; h++) {
                const int gm = gm0 + h * 8;
                float v0 = c[h * 2 + 0], v1 = c[h * 2 + 1];
                if (EPI == 1) {
                    // silu -> fp16
                    float s0 = v0 / (1.f + __expf(-v0));
                    float s1 = v1 / (1.f + __expf(-v1));
                    *(uint32_t*)(Dst + (size_t)gm * N + gn) = packh2(s0, s1);
                } else if (EPI == 2) {
                    // acc * silu(gate) -> fp16
                    __half2 gh = *(const __half2*)(G + (size_t)gm * N + gn);
                    float2 g = __half22float2(gh);
                    *(uint32_t*)(Dst + (size_t)gm * N + gn) = packh2(v0 * g.x, v1 * g.y);
                } else if (EPI == 3) {
                    float2 rr = *(const float2*)(Res + (size_t)gm * N + gn);
                    float2 o; o.x = v0 + rr.x; o.y = v1 + rr.y;
                    *(float2*)(C + (size_t)gm * N + gn) = o;
                } else {  // EPI == 4
                    *(uint32_t*)(Dst + (size_t)gm * N + gn) = packh2(v0, v1);
                }
            }
        }
    }
}

// ---------------- launch ----------------
extern "C" void kernel_launch(void* const* d_in, const int* in_sizes, int n_in,
                              void* d_out, int out_size) {
    const float* x      = (const float*)d_in[0];
    const float* in_w   = (const float*)d_in[2];
    const float* post_w = (const float*)d_in[3];
    const float* Wq     = (const float*)d_in[4];
    const float* Wo     = (const float*)d_in[5];
    const float* Wg     = (const float*)d_in[6];
    const float* Wu     = (const float*)d_in[7];
    const float* Wd     = (const float*)d_in[8];
    float* out = (float*)d_out;

    __half *w16q, *w16o, *w16g, *w16u, *w16d, *a16h, *a16q, *a16p, *a16m, *prod16;
    float *hidden;
    cudaGetSymbolAddress((void**)&w16q, g_w16q);
    cudaGetSymbolAddress((void**)&w16o, g_w16o);
    cudaGetSymbolAddress((void**)&w16g, g_w16g);
    cudaGetSymbolAddress((void**)&w16u, g_w16u);
    cudaGetSymbolAddress((void**)&w16d, g_w16d);
    cudaGetSymbolAddress((void**)&a16h, g_a16h);
    cudaGetSymbolAddress((void**)&a16q, g_a16q);
    cudaGetSymbolAddress((void**)&a16p, g_a16p);
    cudaGetSymbolAddress((void**)&a16m, g_a16m);
    cudaGetSymbolAddress((void**)&prod16, g_prod16);
    cudaGetSymbolAddress((void**)&hidden, g_hidden);

    cudaFuncSetAttribute(gemm_f16<1>, cudaFuncAttributeMaxDynamicSharedMemorySize, SMEM_TOTAL);
    cudaFuncSetAttribute(gemm_f16<2>, cudaFuncAttributeMaxDynamicSharedMemorySize, SMEM_TOTAL);
    cudaFuncSetAttribute(gemm_f16<3>, cudaFuncAttributeMaxDynamicSharedMemorySize, SMEM_TOTAL);
    cudaFuncSetAttribute(gemm_f16<4>, cudaFuncAttributeMaxDynamicSharedMemorySize, SMEM_TOTAL);

    // segment prefix sums (uint4 units = 8 halfs)
    const unsigned nqo = (unsigned)((size_t)QD * HID / 8);        // 524288
    const unsigned ngu = (unsigned)((size_t)INTER_N * HID / 8);   // 2801664
    const unsigned e0 = nqo, e1 = 2 * nqo, e2 = e1 + ngu, e3 = e2 + ngu;
    const unsigned total8 = e3 + ngu;

    const int MT = T_TOK / 128;  // 32

    // 0: input_layernorm -> fp16
    rmsnorm_f16_kernel<<<T_TOK, 256>>>(x, in_w, a16h);
    // 1: all weight converts in one launch (18 grid-stride iters/thread)
    cvt_all_kernel<<<2048, 256>>>((const float4*)Wq, (uint4*)w16q,
                                  (const float4*)Wo, (uint4*)w16o,
                                  (const float4*)Wg, (uint4*)w16g,
                                  (const float4*)Wu, (uint4*)w16u,
                                  (const float4*)Wd, (uint4*)w16d,
                                  e0, e1, e2, e3, total8);
    // 2: q = hnorm @ Wq^T -> fp16
    gemm_f16<4><<<dim3(QD / 128, MT), 128, SMEM_TOTAL>>>(a16h, w16q, nullptr, nullptr, a16q, nullptr, QD, HID);
    // 3: hidden = x + q @ Wo^T
    gemm_f16<3><<<dim3(HID / 128, MT), 128, SMEM_TOTAL>>>(a16q, w16o, hidden, x, nullptr, nullptr, HID, QD);
    // 4: post_attention_layernorm -> fp16
    rmsnorm_f16_kernel<<<T_TOK, 256>>>(hidden, post_w, a16p);
    // 5: prod16 = silu(hpost @ Wg^T)  (fp16)
    gemm_f16<1><<<dim3((INTER_N + 127) / 128, MT), 128, SMEM_TOTAL>>>(a16p, w16g, nullptr, nullptr, prod16, nullptr, INTER_N, HID);
    // 6: a16m = fp16(prod16 * (hpost @ Wu^T))
    gemm_f16<2><<<dim3((INTER_N + 127) / 128, MT), 128, SMEM_TOTAL>>>(a16p, w16u, nullptr, nullptr, a16m, prod16, INTER_N, HID);
    // 7: out = hidden + a16m @ Wd^T
    gemm_f16<3><<<dim3(HID / 128, MT), 128, SMEM_TOTAL>>>(a16m, w16d, out, hidden, nullptr, nullptr, HID, INTER_N);
}

// round 16
// speedup vs baseline: 2.7256x; 1.0043x over previous
#include <cuda_runtime.h>
#include <cuda_fp16.h>
#include <cstdint>

#define T_TOK 4096
#define HID   2048
#define QD    2048
#define INTER_N 10944

// ---------------- scratch (__device__ globals; no allocs allowed) ----------------
__device__ __half g_w16q[(size_t)QD * HID];
__device__ __half g_w16o[(size_t)HID * QD];
__device__ __half g_w16g[(size_t)INTER_N * HID];
__device__ __half g_w16u[(size_t)INTER_N * HID];
__device__ __half g_w16d[(size_t)HID * INTER_N];
__device__ __half g_a16h[(size_t)T_TOK * HID];     // rmsnorm(x) fp16
__device__ __half g_a16q[(size_t)T_TOK * QD];      // q fp16
__device__ __half g_a16p[(size_t)T_TOK * HID];     // rmsnorm(hidden) fp16
__device__ __half g_a16m[(size_t)T_TOK * INTER_N]; // silu(gate)*up fp16
__device__ __half g_prod16[(size_t)T_TOK * INTER_N]; // silu(gate) fp16
__device__ float g_hidden[(size_t)T_TOK * HID];

// ---------------- PTX helpers ----------------
__device__ __forceinline__ uint32_t smem_u32(const void* p) {
    uint32_t a;
    asm("{ .reg .u64 t; cvta.to.shared.u64 t, %1; cvt.u32.u64 %0, t; }" : "=r"(a) : "l"(p));
    return a;
}
#define CP16(dst, src)   asm volatile("cp.async.cg.shared.global [%0], [%1], 16;" :: "r"(dst), "l"(src) : "memory")
#define CP_COMMIT()      asm volatile("cp.async.commit_group;" ::: "memory")
#define CP_WAIT1()       asm volatile("cp.async.wait_group 1;" ::: "memory")

__device__ __forceinline__ void ldm_x4(uint32_t* r, uint32_t addr) {
    asm volatile("ldmatrix.sync.aligned.m8n8.x4.shared.b16 {%0,%1,%2,%3}, [%4];"
                 : "=r"(r[0]), "=r"(r[1]), "=r"(r[2]), "=r"(r[3]) : "r"(addr));
}
__device__ __forceinline__ void mma_fp16(float* c, const uint32_t* a, const uint32_t* b) {
    asm volatile(
        "mma.sync.aligned.m16n8k16.row.col.f32.f16.f16.f32 "
        "{%0,%1,%2,%3}, {%4,%5,%6,%7}, {%8,%9}, {%0,%1,%2,%3};"
        : "+f"(c[0]), "+f"(c[1]), "+f"(c[2]), "+f"(c[3])
        : "r"(a[0]), "r"(a[1]), "r"(a[2]), "r"(a[3]), "r"(b[0]), "r"(b[1]));
}
__device__ __forceinline__ uint32_t packh2(float a, float b) {
    __half2 h = __floats2half2_rn(a, b);
    return *(uint32_t*)&h;
}

// ---------------- single fused weight convert: all 5 weights, fp32 -> fp16 ----------------
__global__ void cvt_all_kernel(const float4* __restrict__ Wq, uint4* __restrict__ Oq,
                               const float4* __restrict__ Wo, uint4* __restrict__ Oo,
                               const float4* __restrict__ Wg, uint4* __restrict__ Og,
                               const float4* __restrict__ Wu, uint4* __restrict__ Ou,
                               const float4* __restrict__ Wd, uint4* __restrict__ Od,
                               unsigned e0, unsigned e1, unsigned e2, unsigned e3,
                               unsigned total8) {
    unsigned i = blockIdx.x * blockDim.x + threadIdx.x;
    const unsigned stride = gridDim.x * blockDim.x;
    for (; i < total8; i += stride) {
        const float4* s; uint4* d; unsigned off;
        if (i < e0)      { s = Wq; d = Oq; off = i; }
        else if (i < e1) { s = Wo; d = Oo; off = i - e0; }
        else if (i < e2) { s = Wg; d = Og; off = i - e1; }
        else if (i < e3) { s = Wu; d = Ou; off = i - e2; }
        else             { s = Wd; d = Od; off = i - e3; }
        float4 v0 = s[off * 2];
        float4 v1 = s[off * 2 + 1];
        uint4 o;
        o.x = packh2(v0.x, v0.y); o.y = packh2(v0.z, v0.w);
        o.z = packh2(v1.x, v1.y); o.w = packh2(v1.z, v1.w);
        d[off] = o;
    }
}

// ---------------- RMSNorm -> fp16 ----------------
__global__ void rmsnorm_f16_kernel(const float* __restrict__ x,
                                   const float* __restrict__ w,
                                   __half* __restrict__ out) {
    const int row = blockIdx.x;
    const float4* xr = (const float4*)(x + (size_t)row * HID);
    const float4* wv4 = (const float4*)w;

    float4 v[2];
    float ss = 0.f;
#pragma unroll
    for (int i = 0; i < 2; i++) {
        v[i] = xr[threadIdx.x + i * 256];
        ss += v[i].x * v[i].x + v[i].y * v[i].y + v[i].z * v[i].z + v[i].w * v[i].w;
    }
#pragma unroll
    for (int o = 16; o; o >>= 1) ss += __shfl_xor_sync(0xffffffffu, ss, o);
    __shared__ float sred[8];
    if ((threadIdx.x & 31) == 0) sred[threadIdx.x >> 5] = ss;
    __syncthreads();
    if (threadIdx.x < 8) {
        float t = sred[threadIdx.x];
#pragma unroll
        for (int o = 4; o; o >>= 1) t += __shfl_xor_sync(0xffu, t, o);
        if (threadIdx.x == 0) sred[0] = t;
    }
    __syncthreads();
    const float scale = rsqrtf(sred[0] * (1.0f / HID) + 1e-6f);

    uint2* orow = (uint2*)(out + (size_t)row * HID);
#pragma unroll
    for (int i = 0; i < 2; i++) {
        float4 wv = wv4[threadIdx.x + i * 256];
        uint2 o;
        o.x = packh2(v[i].x * scale * wv.x, v[i].y * scale * wv.y);
        o.y = packh2(v[i].z * scale * wv.z, v[i].w * scale * wv.w);
        orow[threadIdx.x + i * 256] = o;
    }
}

// ---------------- HMMA GEMM: C[m,n] = epi(sum_k A[m,k]*B[n,k]), fp16 ----------------
// CTA tile 128x128, 128 threads (4 warps, 2m x 2n), warp tile 64x64, BK=64.
// 3-stage cp.async pipeline (96KB smem, 2 CTAs/SM), SW128 swizzle,
// R14-proven mainloop (wait -> barrier -> loads -> compute).
// NEW: odd-parity CTAs delay ~900 cyc once after prologue so co-resident CTA
// pairs anti-align their chunk phases and cover each other's tensor-pipe bubble.
// EPI: 1 = silu -> Dst(f16) ; 2 = acc*G -> Dst(f16) ; 3 = acc+Res -> C(f32) ; 4 = Dst(f16)
#define NSTAGE 3
#define A_BYTES 16384               // 128 rows * 128B
#define STG     32768               // A 16KB + B 16KB
#define SMEM_TOTAL (NSTAGE * STG)   // 96KB

template <int EPI>
__global__ void __launch_bounds__(128, 2)
gemm_f16(const __half* __restrict__ A, const __half* __restrict__ B,
         float* __restrict__ C, const float* __restrict__ Res,
         __half* __restrict__ Dst, const __half* __restrict__ G, int N, int K) {
    extern __shared__ __align__(1024) char smem[];
    const uint32_t sb = smem_u32(smem);
    const int tid = threadIdx.x;
    const int lane = tid & 31;
    const int w = tid >> 5;
    const int mw = w >> 1;            // 0..1  (64-row slab)
    const int nw = w & 1;             // 0..1  (64-col slab)
    const int bm = blockIdx.y * 128;
    const int bn = blockIdx.x * 128;
    const int nch = K >> 6;           // 64-elem chunks
    const uint32_t strideK = (uint32_t)K;
    const uint32_t rowskip16 = strideK * 32u;   // 16 rows * K halves * 2B

    // ---- loader: 16 x 16B per thread (8 for A, 8 for B); strided form ----
    const char* Abase = (const char*)A;
    const char* Bbase = (const char*)B;
    const int lr = tid >> 3;                    // 0..15
    const int lc = tid & 7;                     // 0..7
    const uint32_t l_dst0 = (uint32_t)(lr * 128 + ((lc * 16) ^ ((lr & 7) << 4)));
    const uint32_t a_off0 = ((uint32_t)(bm + lr) * strideK + (uint32_t)lc * 8u) * 2u;
    uint32_t b_off[8];
#pragma unroll
    for (int i = 0; i < 8; i++) {
        int gr = bn + lr + 16 * i; if (gr > N - 1) gr = N - 1;
        b_off[i] = ((uint32_t)gr * strideK + (uint32_t)lc * 8u) * 2u;
    }

    auto load_stage = [&](int stage, int ch) {
        const uint32_t co = (uint32_t)ch * 128u;   // 64 halfs = 128 bytes
        uint32_t ab = sb + stage * STG + l_dst0;
        uint32_t bb = ab + A_BYTES;
        const char* ap = Abase + a_off0 + co;
        const char* bp = Bbase + co;
#pragma unroll
        for (int i = 0; i < 8; i++) CP16(ab + (uint32_t)(i * 2048), ap + (size_t)i * rowskip16);
#pragma unroll
        for (int i = 0; i < 8; i++) CP16(bb + (uint32_t)(i * 2048), bp + b_off[i]);
        CP_COMMIT();
    };

    // ---- ldmatrix lane addressing ----
    const int arow = mw * 64 + (lane & 15);
    const uint32_t a_xor = (uint32_t)((arow & 7) << 4);
    const uint32_t a_rb = (uint32_t)(arow * 128);
    const uint32_t a_k0 = (uint32_t)((lane >> 4) * 16);
    const int brow = nw * 64 + ((lane >> 4) & 1) * 8 + (lane & 7);
    const uint32_t b_xor = (uint32_t)((brow & 7) << 4);
    const uint32_t b_rb = (uint32_t)(brow * 128);
    const uint32_t b_k0 = (uint32_t)(((lane >> 3) & 1) * 16);

    float acc[4][8][4];
#pragma unroll
    for (int i = 0; i < 4; i++)
#pragma unroll
        for (int j = 0; j < 8; j++)
#pragma unroll
            for (int q = 0; q < 4; q++) acc[i][j][q] = 0.f;

    uint32_t af[2][4][4], bf[2][4][4];

    // ---- pipeline prologue (loads in flight during the stagger spin) ----
    load_stage(0, 0);
    load_stage(1, 1);

    // Phase stagger: odd-parity CTAs idle ~900 cycles (half a chunk period) so
    // the two co-resident CTAs on an SM anti-align and cover each other's
    // wait/barrier/prime bubble on the tensor pipe.
    if (((blockIdx.x ^ blockIdx.y) & 1) != 0) {
        long long t0 = clock64();
        while (clock64() - t0 < 900) { }
    }

    for (int s = 0; s < nch; s++) {
        const int stage = s % NSTAGE;
        CP_WAIT1();                   // chunk s resident (this thread's groups)
        __syncthreads();              // make all threads' waits mutually visible;
                                      // stage (s+2)%3 now free for reuse

        const int nc = s + 2;
        if (nc < nch) load_stage(nc % NSTAGE, nc);
        else          CP_COMMIT();    // empty group keeps wait accounting exact

        const uint32_t sA = sb + stage * STG;
        const uint32_t sB = sA + A_BYTES;

        // prime kk=0 fragments
#pragma unroll
        for (int ma = 0; ma < 4; ma++)
            ldm_x4(af[0][ma], sA + a_rb + (uint32_t)(ma * 2048) + (a_k0 ^ a_xor));
#pragma unroll
        for (int nb = 0; nb < 4; nb++)
            ldm_x4(bf[0][nb], sB + b_rb + (uint32_t)(nb * 2048) + (b_k0 ^ b_xor));

#pragma unroll
        for (int kk = 0; kk < 4; kk++) {
            const int cur = kk & 1, nxt = cur ^ 1;
            if (kk < 3) {   // prefetch next kk's fragments under this kk's MMAs
#pragma unroll
                for (int ma = 0; ma < 4; ma++)
                    ldm_x4(af[nxt][ma], sA + a_rb + (uint32_t)(ma * 2048) + (((kk + 1) * 32 + a_k0) ^ a_xor));
#pragma unroll
                for (int nb = 0; nb < 4; nb++)
                    ldm_x4(bf[nxt][nb], sB + b_rb + (uint32_t)(nb * 2048) + (((kk + 1) * 32 + b_k0) ^ b_xor));
            }
#pragma unroll
            for (int ma = 0; ma < 4; ma++)
#pragma unroll
                for (int na = 0; na < 8; na++)
                    mma_fp16(acc[ma][na], af[cur][ma], &bf[cur][na >> 1][(na & 1) * 2]);
        }
    }

    // ---- epilogue ----
#pragma unroll
    for (int ma = 0; ma < 4; ma++) {
        const int gm0 = bm + mw * 64 + ma * 16 + (lane >> 2);
#pragma unroll
        for (int na = 0; na < 8; na++) {
            const int gn = bn + nw * 64 + na * 8 + (lane & 3) * 2;
            if (gn >= N) continue;
            const float* c = acc[ma][na];
#pragma unroll
            for (int h = 0; h < 2; h++) {
                const int gm = gm0 + h * 8;
                float v0 = c[h * 2 + 0], v1 = c[h * 2 + 1];
                if (EPI == 1) {
                    // silu -> fp16
                    float s0 = v0 / (1.f + __expf(-v0));
                    float s1 = v1 / (1.f + __expf(-v1));
                    *(uint32_t*)(Dst + (size_t)gm * N + gn) = packh2(s0, s1);
                } else if (EPI == 2) {
                    // acc * silu(gate) -> fp16
                    __half2 gh = *(const __half2*)(G + (size_t)gm * N + gn);
                    float2 g = __half22float2(gh);
                    *(uint32_t*)(Dst + (size_t)gm * N + gn) = packh2(v0 * g.x, v1 * g.y);
                } else if (EPI == 3) {
                    float2 rr = *(const float2*)(Res + (size_t)gm * N + gn);
                    float2 o; o.x = v0 + rr.x; o.y = v1 + rr.y;
                    *(float2*)(C + (size_t)gm * N + gn) = o;
                } else {  // EPI == 4
                    *(uint32_t*)(Dst + (size_t)gm * N + gn) = packh2(v0, v1);
                }
            }
        }
    }
}

// ---------------- launch ----------------
extern "C" void kernel_launch(void* const* d_in, const int* in_sizes, int n_in,
                              void* d_out, int out_size) {
    const float* x      = (const float*)d_in[0];
    const float* in_w   = (const float*)d_in[2];
    const float* post_w = (const float*)d_in[3];
    const float* Wq     = (const float*)d_in[4];
    const float* Wo     = (const float*)d_in[5];
    const float* Wg     = (const float*)d_in[6];
    const float* Wu     = (const float*)d_in[7];
    const float* Wd     = (const float*)d_in[8];
    float* out = (float*)d_out;

    __half *w16q, *w16o, *w16g, *w16u, *w16d, *a16h, *a16q, *a16p, *a16m, *prod16;
    float *hidden;
    cudaGetSymbolAddress((void**)&w16q, g_w16q);
    cudaGetSymbolAddress((void**)&w16o, g_w16o);
    cudaGetSymbolAddress((void**)&w16g, g_w16g);
    cudaGetSymbolAddress((void**)&w16u, g_w16u);
    cudaGetSymbolAddress((void**)&w16d, g_w16d);
    cudaGetSymbolAddress((void**)&a16h, g_a16h);
    cudaGetSymbolAddress((void**)&a16q, g_a16q);
    cudaGetSymbolAddress((void**)&a16p, g_a16p);
    cudaGetSymbolAddress((void**)&a16m, g_a16m);
    cudaGetSymbolAddress((void**)&prod16, g_prod16);
    cudaGetSymbolAddress((void**)&hidden, g_hidden);

    cudaFuncSetAttribute(gemm_f16<1>, cudaFuncAttributeMaxDynamicSharedMemorySize, SMEM_TOTAL);
    cudaFuncSetAttribute(gemm_f16<2>, cudaFuncAttributeMaxDynamicSharedMemorySize, SMEM_TOTAL);
    cudaFuncSetAttribute(gemm_f16<3>, cudaFuncAttributeMaxDynamicSharedMemorySize, SMEM_TOTAL);
    cudaFuncSetAttribute(gemm_f16<4>, cudaFuncAttributeMaxDynamicSharedMemorySize, SMEM_TOTAL);

    // segment prefix sums (uint4 units = 8 halfs)
    const unsigned nqo = (unsigned)((size_t)QD * HID / 8);        // 524288
    const unsigned ngu = (unsigned)((size_t)INTER_N * HID / 8);   // 2801664
    const unsigned e0 = nqo, e1 = 2 * nqo, e2 = e1 + ngu, e3 = e2 + ngu;
    const unsigned total8 = e3 + ngu;

    const int MT = T_TOK / 128;  // 32

    // 0: input_layernorm -> fp16
    rmsnorm_f16_kernel<<<T_TOK, 256>>>(x, in_w, a16h);
    // 1: all weight converts in one launch
    cvt_all_kernel<<<2048, 256>>>((const float4*)Wq, (uint4*)w16q,
                                  (const float4*)Wo, (uint4*)w16o,
                                  (const float4*)Wg, (uint4*)w16g,
                                  (const float4*)Wu, (uint4*)w16u,
                                  (const float4*)Wd, (uint4*)w16d,
                                  e0, e1, e2, e3, total8);
    // 2: q = hnorm @ Wq^T -> fp16
    gemm_f16<4><<<dim3(QD / 128, MT), 128, SMEM_TOTAL>>>(a16h, w16q, nullptr, nullptr, a16q, nullptr, QD, HID);
    // 3: hidden = x + q @ Wo^T   (ncu -s 5 window lands in GEMM territory)
    gemm_f16<3><<<dim3(HID / 128, MT), 128, SMEM_TOTAL>>>(a16q, w16o, hidden, x, nullptr, nullptr, HID, QD);
    // 4: post_attention_layernorm -> fp16
    rmsnorm_f16_kernel<<<T_TOK, 256>>>(hidden, post_w, a16p);
    // 5: prod16 = silu(hpost @ Wg^T)  (fp16)
    gemm_f16<1><<<dim3((INTER_N + 127) / 128, MT), 128, SMEM_TOTAL>>>(a16p, w16g, nullptr, nullptr, prod16, nullptr, INTER_N, HID);
    // 6: a16m = fp16(prod16 * (hpost @ Wu^T))
    gemm_f16<2><<<dim3((INTER_N + 127) / 128, MT), 128, SMEM_TOTAL>>>(a16p, w16u, nullptr, nullptr, a16m, prod16, INTER_N, HID);
    // 7: out = hidden + a16m @ Wd^T
    gemm_f16<3><<<dim3(HID / 128, MT), 128, SMEM_TOTAL>>>(a16m, w16d, out, hidden, nullptr, nullptr, HID, INTER_N);
}